// round 3
// baseline (speedup 1.0000x reference)
#include <cuda_runtime.h>

#define NP 8192
#define THREADS 128
#define IPT 4
#define IB (NP / (THREADS * IPT))   // 16 i-blocks (512 i's each)
#define JC 16
#define JCHUNK (NP / JC)            // 512 j's per chunk
#define JP (JCHUNK / 2)             // 256 packed j-pair iterations

static_assert(IB * THREADS * IPT == NP, "i coverage");
static_assert(JC * JCHUNK == NP, "j coverage");

typedef unsigned long long u64;

// Scratch: [i][jc] -> {sum, cnt}. Every slot written exactly once per launch.
__device__ float2 g_part[NP * JC];

__device__ __forceinline__ u64 pk2(float lo, float hi) {
    u64 r; asm("mov.b64 %0, {%1, %2};" : "=l"(r) : "f"(lo), "f"(hi)); return r;
}
__device__ __forceinline__ void upk2(u64 v, float& lo, float& hi) {
    asm("mov.b64 {%0, %1}, %2;" : "=f"(lo), "=f"(hi) : "l"(v));
}
__device__ __forceinline__ u64 fma2(u64 a, u64 b, u64 c) {
    u64 r; asm("fma.rn.f32x2 %0, %1, %2, %3;" : "=l"(r) : "l"(a), "l"(b), "l"(c)); return r;
}
__device__ __forceinline__ u64 mul2(u64 a, u64 b) {
    u64 r; asm("mul.rn.f32x2 %0, %1, %2;" : "=l"(r) : "l"(a), "l"(b)); return r;
}
__device__ __forceinline__ u64 add2(u64 a, u64 b) {
    u64 r; asm("add.rn.f32x2 %0, %1, %2;" : "=l"(r) : "l"(a), "l"(b)); return r;
}
__device__ __forceinline__ float sqa(float x) {
    float r; asm("sqrt.approx.f32 %0, %1;" : "=f"(r) : "f"(x)); return r;
}

#define T35 0.70020753f  // tan(35 deg)

__global__ __launch_bounds__(THREADS)
void pair_kernel(const float2* __restrict__ past, const float2* __restrict__ pos) {
    __shared__ float2 sj[JCHUNK];
    const int ib = blockIdx.x;
    const int jc = blockIdx.y;
    const int tid = threadIdx.x;
    const int jbase = jc * JCHUNK;

    for (int t = tid; t < JCHUNK; t += THREADS) sj[t] = pos[jbase + t];
    __syncthreads();

    const int i0 = ib * (THREADS * IPT);

    float c[IPT], s[IPT], a[IPT], b[IPT];
    u64 c2[IPT], s2[IPT], ns2[IPT], a2[IPT], b2[IPT], sum2[IPT], cnt2[IPT];
    int ii[IPT];

    #pragma unroll
    for (int k = 0; k < IPT; k++) {
        const int i = i0 + k * THREADS + tid;
        ii[k] = i;
        const float2 p = pos[i];
        const float2 q = past[i];
        const float dx = p.x - q.x;
        const float dy = p.y - q.y;
        const float l2 = fmaf(dx, dx, dy * dy);
        float rin; asm("rsqrt.approx.f32 %0, %1;" : "=f"(rin) : "f"(l2));
        const float ci = (l2 > 0.0f) ? dx * rin : 1.0f;
        const float si = (l2 > 0.0f) ? dy * rin : 0.0f;
        c[k] = ci; s[k] = si;
        a[k] = -fmaf(p.x, ci, p.y * si);     // -(x_i*c + y_i*s)
        b[k] =  fmaf(p.x, si, -(p.y * ci));  //  x_i*s - y_i*c
        c2[k]  = pk2(ci, ci);
        s2[k]  = pk2(si, si);
        ns2[k] = pk2(-si, -si);
        a2[k]  = pk2(a[k], a[k]);
        b2[k]  = pk2(b[k], b[k]);
        sum2[k] = 0ull;
        cnt2[k] = 0ull;
    }

    const u64 T2 = pk2(T35, T35);
    const float4* __restrict__ sj4 = (const float4*)sj;

    for (int jj = 0; jj < JP; jj++) {
        const float4 pj = sj4[jj];              // {x0, y0, x1, y1}
        const u64 px = pk2(pj.x, pj.z);
        const u64 py = pk2(pj.y, pj.w);
        #pragma unroll
        for (int k = 0; k < IPT; k++) {
            const u64 xp = fma2(px, c2[k], fma2(py, s2[k],  a2[k]));
            const u64 yp = fma2(py, c2[k], fma2(px, ns2[k], b2[k]));
            const u64 tt = mul2(xp, T2);
            const u64 sq = fma2(xp, xp, mul2(yp, yp));
            float sl, sh, yl, yh, tl, th;
            upk2(sq, sl, sh); upk2(yp, yl, yh); upk2(tt, tl, th);
            const float dl = sqa(sl);
            const float dh = sqa(sh);
            const bool vl = fabsf(yl) < tl;   // implies xp>0
            const bool vh = fabsf(yh) < th;
            sum2[k] = add2(sum2[k], pk2(vl ? dl : 0.0f, vh ? dh : 0.0f));
            cnt2[k] = add2(cnt2[k], pk2(vl ? 1.0f : 0.0f, vh ? 1.0f : 0.0f));
        }
    }

    #pragma unroll
    for (int k = 0; k < IPT; k++) {
        float sl, sh, cl, ch;
        upk2(sum2[k], sl, sh);
        upk2(cnt2[k], cl, ch);
        float sum = sl + sh;
        float cnt = cl + ch;
        const int i = ii[k];
        // Self-pair was counted in the loop (xp~0,yp~0 may pass the strict test);
        // recompute its contribution bitwise-identically and remove it.
        if (i >= jbase && i < jbase + JCHUNK) {
            const float2 p = sj[i - jbase];
            const float xp = fmaf(p.x, c[k], fmaf(p.y, s[k], a[k]));
            const float yv = fmaf(p.y, c[k], fmaf(p.x, -s[k], b[k]));
            const float tv = xp * T35;
            const float sv = fmaf(xp, xp, yv * yv);
            const float dv = sqa(sv);
            if (fabsf(yv) < tv) { sum -= dv; cnt -= 1.0f; }
        }
        g_part[i * JC + jc] = make_float2(sum, cnt);
    }
}

__global__ void finalize_kernel(const int* __restrict__ idxmask,
                                const float* __restrict__ radii,
                                float* __restrict__ out) {
    const int i = blockIdx.x * blockDim.x + threadIdx.x;
    const float4* __restrict__ p = (const float4*)(g_part + i * JC);
    float s = 0.0f, c = 0.0f;
    #pragma unroll
    for (int q = 0; q < JC / 2; q++) {
        const float4 v = p[q];                 // {sum0, cnt0, sum1, cnt1}
        s += v.x + v.z;
        c += v.y + v.w;
    }
    float mean = (c > 0.0f) ? s / c : 0.0f;
    mean = fminf(fmaxf(mean, 0.2f), 5.0f);     // clip [MIN_D, MAX_D]
    const float reg = (mean - 0.2f) * (1.0f / 4.8f);
    const float r = fmaf(reg, 3.5f, 0.5f);     // MIN_R + reg*(MAX_R-MIN_R)
    out[i] = idxmask[i] ? r : radii[i];
}

extern "C" void kernel_launch(void* const* d_in, const int* in_sizes, int n_in,
                              void* d_out, int out_size) {
    const float2* past = (const float2*)d_in[0];
    const float2* pos  = (const float2*)d_in[1];
    const int* idxm    = (const int*)d_in[2];   // bool widened to int32
    const float* radii = (const float*)d_in[3];
    float* out = (float*)d_out;

    dim3 grid(IB, JC);
    pair_kernel<<<grid, THREADS>>>(past, pos);
    finalize_kernel<<<NP / 128, 128>>>(idxm, radii, out);
}

// round 4
// speedup vs baseline: 1.1344x; 1.1344x over previous
#include <cuda_runtime.h>

#define NP 8192
#define THREADS 128
#define IPT 2
#define IB (NP / (THREADS * IPT))   // 32 i-blocks (256 i's each)
#define JC 16
#define JCHUNK (NP / JC)            // 512 j's per chunk
#define JP (JCHUNK / 2)             // 256 packed j-pair iterations

static_assert(IB * THREADS * IPT == NP, "i coverage");
static_assert(JC * JCHUNK == NP, "j coverage");

typedef unsigned long long u64;

// Scratch: [i][jc] -> {sum, cnt}. Every slot written exactly once per launch.
__device__ float2 g_part[NP * JC];

__device__ __forceinline__ u64 pk2(float lo, float hi) {
    u64 r; asm("mov.b64 %0, {%1, %2};" : "=l"(r) : "f"(lo), "f"(hi)); return r;
}
__device__ __forceinline__ void upk2(u64 v, float& lo, float& hi) {
    asm("mov.b64 {%0, %1}, %2;" : "=f"(lo), "=f"(hi) : "l"(v));
}
__device__ __forceinline__ u64 fma2(u64 a, u64 b, u64 c) {
    u64 r; asm("fma.rn.f32x2 %0, %1, %2, %3;" : "=l"(r) : "l"(a), "l"(b), "l"(c)); return r;
}
__device__ __forceinline__ u64 mul2(u64 a, u64 b) {
    u64 r; asm("mul.rn.f32x2 %0, %1, %2;" : "=l"(r) : "l"(a), "l"(b)); return r;
}
__device__ __forceinline__ float sqa(float x) {
    float r; asm("sqrt.approx.f32 %0, %1;" : "=f"(r) : "f"(x)); return r;
}

#define T35   0.70020753f            // tan(35 deg)
#define INVT  1.4281480f             // 1/tan(35 deg)
__device__ __constant__ float TTc = T35 * T35;  // compile-time float

__global__ void noop_kernel() {}

__global__ __launch_bounds__(THREADS)
void pair_kernel(const float2* __restrict__ past, const float2* __restrict__ pos) {
    // Pre-paired SoA: sx[m] packs {x(2m), x(2m+1)}, sy[m] packs {y(2m), y(2m+1)}
    __shared__ u64 sx[JP], sy[JP];
    const int ib = blockIdx.x;
    const int jc = blockIdx.y;
    const int tid = threadIdx.x;
    const int jbase = jc * JCHUNK;

    for (int t = tid; t < JCHUNK; t += THREADS) {
        const float2 p = pos[jbase + t];
        ((float*)sx)[t] = p.x;
        ((float*)sy)[t] = p.y;
    }
    __syncthreads();

    const int i0 = ib * (THREADS * IPT);
    const float TT = T35 * T35;

    float c_[IPT], s_[IPT], a_[IPT], ct_[IPT], nst_[IPT], bt_[IPT];
    u64 c2[IPT], s2[IPT], a2[IPT], ct2[IPT], nst2[IPT], bt2[IPT];
    float sum0[IPT], sum1[IPT];
    int cnt0[IPT], cnt1[IPT], ii[IPT];

    #pragma unroll
    for (int k = 0; k < IPT; k++) {
        const int i = i0 + k * THREADS + tid;
        ii[k] = i;
        const float2 p = pos[i];
        const float2 q = past[i];
        const float dx = p.x - q.x;
        const float dy = p.y - q.y;
        const float l2 = fmaf(dx, dx, dy * dy);
        float rin; asm("rsqrt.approx.f32 %0, %1;" : "=f"(rin) : "f"(l2));
        const float ci = (l2 > 0.0f) ? dx * rin : 1.0f;
        const float si = (l2 > 0.0f) ? dy * rin : 0.0f;
        const float av = -fmaf(p.x, ci, p.y * si);     // -(x c + y s)
        const float bv =  fmaf(p.x, si, -(p.y * ci));  //  x s - y c
        // y-row scaled by 1/T so the arc test is |yb| < xp (no per-pair mul)
        const float ctv  =  ci * INVT;
        const float nstv = -si * INVT;
        const float btv  =  bv * INVT;
        c_[k] = ci; s_[k] = si; a_[k] = av;
        ct_[k] = ctv; nst_[k] = nstv; bt_[k] = btv;
        c2[k]  = pk2(ci, ci);    s2[k]   = pk2(si, si);   a2[k]  = pk2(av, av);
        ct2[k] = pk2(ctv, ctv);  nst2[k] = pk2(nstv, nstv); bt2[k] = pk2(btv, btv);
        sum0[k] = 0.0f; sum1[k] = 0.0f; cnt0[k] = 0; cnt1[k] = 0;
    }

    const u64 TT2 = pk2(TT, TT);

    #pragma unroll 4
    for (int jj = 0; jj < JP; jj++) {
        const u64 px2 = sx[jj];
        const u64 py2 = sy[jj];
        #pragma unroll
        for (int k = 0; k < IPT; k++) {
            const u64 xp2 = fma2(px2, c2[k],  fma2(py2, s2[k],   a2[k]));
            const u64 yb2 = fma2(py2, ct2[k], fma2(px2, nst2[k], bt2[k]));
            const u64 sq2 = fma2(mul2(TT2, yb2), yb2, mul2(xp2, xp2));
            float xl, xh, yl, yh, sl, sh;
            upk2(xp2, xl, xh); upk2(yb2, yl, yh); upk2(sq2, sl, sh);
            const float dl = sqa(sl);
            const float dh = sqa(sh);
            if (fabsf(yl) < xl) { sum0[k] += dl; cnt0[k]++; }  // implies xp>0
            if (fabsf(yh) < xh) { sum1[k] += dh; cnt1[k]++; }
        }
    }

    #pragma unroll
    for (int k = 0; k < IPT; k++) {
        float sA = sum0[k], sB = sum1[k];
        int   cA = cnt0[k], cB = cnt1[k];
        const int i = ii[k];
        // Remove self-pair if it slipped past the strict test; recompute the
        // contribution with bitwise-identical arithmetic and subtract.
        if (i >= jbase && i < jbase + JCHUNK) {
            const int loc = i - jbase;
            const float pxs = ((const float*)sx)[loc];
            const float pys = ((const float*)sy)[loc];
            const float xp = fmaf(pxs, c_[k],  fmaf(pys, s_[k],   a_[k]));
            const float yb = fmaf(pys, ct_[k], fmaf(pxs, nst_[k], bt_[k]));
            const float sq = fmaf(TT * yb, yb, xp * xp);
            const float dv = sqa(sq);
            if (fabsf(yb) < xp) {
                if (loc & 1) { sB -= dv; cB--; } else { sA -= dv; cA--; }
            }
        }
        g_part[i * JC + jc] = make_float2(sA + sB, (float)(cA + cB));
    }
}

__global__ __launch_bounds__(32)
void finalize_kernel(const int* __restrict__ idxmask,
                     const float* __restrict__ radii,
                     float* __restrict__ out) {
    const int i = blockIdx.x * 32 + threadIdx.x;
    const float4* __restrict__ p = (const float4*)(g_part + i * JC);
    float s = 0.0f, c = 0.0f;
    #pragma unroll
    for (int q = 0; q < JC / 2; q++) {
        const float4 v = p[q];                 // {sum0, cnt0, sum1, cnt1}
        s += v.x + v.z;
        c += v.y + v.w;
    }
    float mean = (c > 0.0f) ? s / c : 0.0f;
    mean = fminf(fmaxf(mean, 0.2f), 5.0f);     // clip [MIN_D, MAX_D]
    const float reg = (mean - 0.2f) * (1.0f / 4.8f);
    const float r = fmaf(reg, 3.5f, 0.5f);     // MIN_R + reg*(MAX_R-MIN_R)
    out[i] = idxmask[i] ? r : radii[i];
}

extern "C" void kernel_launch(void* const* d_in, const int* in_sizes, int n_in,
                              void* d_out, int out_size) {
    const float2* past = (const float2*)d_in[0];
    const float2* pos  = (const float2*)d_in[1];
    const int* idxm    = (const int*)d_in[2];   // bool widened to int32
    const float* radii = (const float*)d_in[3];
    float* out = (float*)d_out;

    // Launch order makes ncu -s 5 -c 1 (launch #6) land on pair_kernel.
    noop_kernel<<<1, 32>>>();
    dim3 grid(IB, JC);
    pair_kernel<<<grid, THREADS>>>(past, pos);
    noop_kernel<<<1, 32>>>();
    finalize_kernel<<<NP / 32, 32>>>(idxm, radii, out);
}